// round 15
// baseline (speedup 1.0000x reference)
#include <cuda_runtime.h>
#include <cstdint>

#define Bz   128
#define Nn   196
#define DIMc 384
#define Kk   16
#define Hh   6
#define TMX  28   // mixer m-tile width per CTA; 7*28 == 196
#define CH2  14   // mixer n-chunk (double-buffered); 14*14 == 196
#define NCH2 14

// Scratch (device globals — allocation-free)
__device__ __align__(16) float    g_wbt[(size_t)Nn * Nn * Kk];      // [n][m][k]
__device__ __align__(16) float    g_mix[(size_t)Bz * Nn * Hh * Kk]; // [b][n][h][k]
__device__ __align__(16) uint32_t g_xtf[(size_t)Bz * Nn * DIMc];    // x as tf32 bits

__device__ __forceinline__ uint32_t tf32r(float f) {
    uint32_t u;
    asm("cvt.rna.tf32.f32 %0, %1;" : "=r"(u) : "f"(f));
    return u;
}
__device__ __forceinline__ void mma_tf32(float* c, uint32_t a0, uint32_t a1,
                                         uint32_t a2, uint32_t a3,
                                         uint32_t b0, uint32_t b1) {
    asm volatile(
        "mma.sync.aligned.m16n8k8.row.col.f32.tf32.tf32.f32 "
        "{%0,%1,%2,%3}, {%4,%5,%6,%7}, {%8,%9}, {%0,%1,%2,%3};"
        : "+f"(c[0]), "+f"(c[1]), "+f"(c[2]), "+f"(c[3])
        : "r"(a0), "r"(a1), "r"(a2), "r"(a3), "r"(b0), "r"(b1));
}
__device__ __forceinline__ uint32_t smem_u32p(const void* p) {
    uint32_t a;
    asm("{ .reg .u64 tmp; cvta.to.shared.u64 tmp, %1; cvt.u32.u64 %0, tmp; }"
        : "=r"(a) : "l"(p));
    return a;
}
__device__ __forceinline__ void cp_async16(uint32_t saddr, const void* gptr) {
    asm volatile("cp.async.ca.shared.global [%0], [%1], 16;"
                 :: "r"(saddr), "l"(gptr) : "memory");
}
#define CP_COMMIT() asm volatile("cp.async.commit_group;" ::: "memory")
#define CP_WAIT(n)  asm volatile("cp.async.wait_group %0;" :: "n"(n) : "memory")

// ---------------------------------------------------------------------------
// Kernel 1: weight_bank [k][n][m] -> g_wbt [n][m][k]  (k contiguous)
// ---------------------------------------------------------------------------
extern "C" __global__ void transpose_wb_kernel(const float* __restrict__ wb) {
    int t = blockIdx.x * 256 + threadIdx.x;
    if (t >= Nn * Nn) return;
    int n = t / Nn, m = t % Nn;
    float v[Kk];
#pragma unroll
    for (int k = 0; k < Kk; ++k)
        v[k] = wb[((size_t)k * Nn + n) * Nn + m];   // coalesced over m
    float4* dst = (float4*)&g_wbt[(size_t)t * Kk];
    dst[0] = make_float4(v[0],  v[1],  v[2],  v[3]);
    dst[1] = make_float4(v[4],  v[5],  v[6],  v[7]);
    dst[2] = make_float4(v[8],  v[9],  v[10], v[11]);
    dst[3] = make_float4(v[12], v[13], v[14], v[15]);
}

// ---------------------------------------------------------------------------
// Kernel 1b: x (fp32) -> g_xtf (tf32 bits, rna) — enables raw cp.async staging
// in the mixer while preserving round-to-nearest tf32 quality.
// ---------------------------------------------------------------------------
#define XTF_F4 ((Bz * Nn * DIMc) / 4)   // 2408448 float4s
extern "C" __global__ void xtf_kernel(const float* __restrict__ x) {
    int idx = blockIdx.x * 256 + threadIdx.x;
    if (idx >= XTF_F4) return;
    float4 v = ((const float4*)x)[idx];
    ((uint4*)g_xtf)[idx] = make_uint4(tf32r(v.x), tf32r(v.y), tf32r(v.z), tf32r(v.w));
}

// ---------------------------------------------------------------------------
// Kernel 2: adapter v5 (tensor, mma.sync tf32). UNCHANGED from R14 (measured).
// ---------------------------------------------------------------------------
#define ATP_A 100
#define ATP_B 104
#define AT_SMEM_BYTES ((64 * ATP_A + 96 * ATP_B) * 4)

extern "C" __global__ void __launch_bounds__(128)
adapter_kernel(const float* __restrict__ x,
               const float* __restrict__ W1, const float* __restrict__ b1,
               const float* __restrict__ W2, const float* __restrict__ b2) {
    extern __shared__ float sm[];
    uint32_t* As = (uint32_t*)sm;                 // [64][100] tf32 bits / logits fp32
    uint32_t* Bs = (uint32_t*)(sm + 64 * ATP_A);  // [96][104] tf32 bits

    const int t    = threadIdx.x;
    const int lane = t & 31;
    const int warp = t >> 5;
    const int row0 = blockIdx.x * 64;

    const int qr = lane >> 2;
    const int qc = lane & 3;

    float acc[12][4];
#pragma unroll
    for (int nt = 0; nt < 12; ++nt)
#pragma unroll
        for (int q = 0; q < 4; ++q) acc[nt][q] = 0.f;

    for (int kc = 0; kc < 4; ++kc) {
        __syncthreads();
        for (int idx = t; idx < 1536; idx += 128) {
            int r = idx / 24, c4 = idx - (idx / 24) * 24;
            float4 v = *(const float4*)&x[(size_t)(row0 + r) * DIMc + kc * 96 + c4 * 4];
            *(uint4*)&As[r * ATP_A + c4 * 4] =
                make_uint4(tf32r(v.x), tf32r(v.y), tf32r(v.z), tf32r(v.w));
        }
        for (int idx = t; idx < 2304; idx += 128) {
            int k = idx / 24, n4 = idx - (idx / 24) * 24;
            float4 v = *(const float4*)&W1[(size_t)(kc * 96 + k) * 96 + n4 * 4];
            *(uint4*)&Bs[k * ATP_B + n4 * 4] =
                make_uint4(tf32r(v.x), tf32r(v.y), tf32r(v.z), tf32r(v.w));
        }
        __syncthreads();
#pragma unroll
        for (int kt = 0; kt < 12; ++kt) {
            int k8 = kt * 8;
            int arow = warp * 16 + qr;
            uint32_t a0 = As[arow * ATP_A + k8 + qc];
            uint32_t a1 = As[(arow + 8) * ATP_A + k8 + qc];
            uint32_t a2 = As[arow * ATP_A + k8 + qc + 4];
            uint32_t a3 = As[(arow + 8) * ATP_A + k8 + qc + 4];
            int bb0 = (k8 + qc) * ATP_B + qr;
            int bb1 = (k8 + qc + 4) * ATP_B + qr;
#pragma unroll
            for (int nt = 0; nt < 12; ++nt) {
                uint32_t b0v = Bs[bb0 + nt * 8];
                uint32_t b1v = Bs[bb1 + nt * 8];
                mma_tf32(acc[nt], a0, a1, a2, a3, b0v, b1v);
            }
        }
    }
    __syncthreads();

    {
        int rlo = warp * 16 + qr, rhi = rlo + 8;
#pragma unroll
        for (int nt = 0; nt < 12; ++nt) {
            int c0 = nt * 8 + 2 * qc, c1 = c0 + 1;
            float g0 = acc[nt][0] + __ldg(&b1[c0]);
            float g1 = acc[nt][1] + __ldg(&b1[c1]);
            float g2 = acc[nt][2] + __ldg(&b1[c0]);
            float g3 = acc[nt][3] + __ldg(&b1[c1]);
            g0 = 0.5f * g0 * (1.0f + erff(g0 * 0.7071067811865476f));
            g1 = 0.5f * g1 * (1.0f + erff(g1 * 0.7071067811865476f));
            g2 = 0.5f * g2 * (1.0f + erff(g2 * 0.7071067811865476f));
            g3 = 0.5f * g3 * (1.0f + erff(g3 * 0.7071067811865476f));
            As[rlo * ATP_A + c0] = tf32r(g0);
            As[rlo * ATP_A + c1] = tf32r(g1);
            As[rhi * ATP_A + c0] = tf32r(g2);
            As[rhi * ATP_A + c1] = tf32r(g3);
        }
        for (int idx = t; idx < 2304; idx += 128) {
            int k = idx / 24, n4 = idx - (idx / 24) * 24;
            float4 v = *(const float4*)&W2[(size_t)k * 96 + n4 * 4];
            *(uint4*)&Bs[k * ATP_B + n4 * 4] =
                make_uint4(tf32r(v.x), tf32r(v.y), tf32r(v.z), tf32r(v.w));
        }
    }
    __syncthreads();

#pragma unroll
    for (int nt = 0; nt < 12; ++nt)
#pragma unroll
        for (int q = 0; q < 4; ++q) acc[nt][q] = 0.f;
#pragma unroll
    for (int kt = 0; kt < 12; ++kt) {
        int k8 = kt * 8;
        int arow = warp * 16 + qr;
        uint32_t a0 = As[arow * ATP_A + k8 + qc];
        uint32_t a1 = As[(arow + 8) * ATP_A + k8 + qc];
        uint32_t a2 = As[arow * ATP_A + k8 + qc + 4];
        uint32_t a3 = As[(arow + 8) * ATP_A + k8 + qc + 4];
        int bb0 = (k8 + qc) * ATP_B + qr;
        int bb1 = (k8 + qc + 4) * ATP_B + qr;
#pragma unroll
        for (int nt = 0; nt < 12; ++nt) {
            uint32_t b0v = Bs[bb0 + nt * 8];
            uint32_t b1v = Bs[bb1 + nt * 8];
            mma_tf32(acc[nt], a0, a1, a2, a3, b0v, b1v);
        }
    }
    __syncthreads();

    {
        float* Lf = (float*)As;
        int rlo = warp * 16 + qr, rhi = rlo + 8;
#pragma unroll
        for (int nt = 0; nt < 12; ++nt) {
            int c0 = nt * 8 + 2 * qc, c1 = c0 + 1;
            Lf[rlo * ATP_A + c0] = acc[nt][0] + __ldg(&b2[c0]);
            Lf[rlo * ATP_A + c1] = acc[nt][1] + __ldg(&b2[c1]);
            Lf[rhi * ATP_A + c0] = acc[nt][2] + __ldg(&b2[c0]);
            Lf[rhi * ATP_A + c1] = acc[nt][3] + __ldg(&b2[c1]);
        }
    }
    __syncthreads();

    {
        const float* Lf = (const float*)As;
        for (int task = t; task < 384; task += 128) {
            int r = task / 6, h = task - (task / 6) * 6;
            float vals[Kk];
            float vmax = -1e30f;
#pragma unroll
            for (int k = 0; k < Kk; ++k) {
                vals[k] = Lf[r * ATP_A + k * Hh + h];
                vmax = fmaxf(vmax, vals[k]);
            }
            float s = 0.f;
#pragma unroll
            for (int k = 0; k < Kk; ++k) { vals[k] = __expf(vals[k] - vmax); s += vals[k]; }
            float inv = 1.0f / s;
            float4* dst = (float4*)&g_mix[(size_t)(row0 + r) * 96 + h * Kk];
            dst[0] = make_float4(vals[0]  * inv, vals[1]  * inv, vals[2]  * inv, vals[3]  * inv);
            dst[1] = make_float4(vals[4]  * inv, vals[5]  * inv, vals[6]  * inv, vals[7]  * inv);
            dst[2] = make_float4(vals[8]  * inv, vals[9]  * inv, vals[10] * inv, vals[11] * inv);
            dst[3] = make_float4(vals[12] * inv, vals[13] * inv, vals[14] * inv, vals[15] * inv);
        }
    }
}

// ---------------------------------------------------------------------------
// Kernel 3: mixer v7 — double-buffered cp.async pipeline, chunks of 14 n.
// CTA = (b, mt of 28 m), 384 threads = 12 warps = 6 h x 2 mtiles(16).
// Per chunk (14 n, padded to 16 = 2 ktiles of 8):
//   prefetch chunk c+1 (xs from g_xtf raw tf32 bits; mix fp32) while chunk c
//   runs phase1 (scalar fp32 dot16 -> ws tf32) + phase2 (mma.sync).
// smem: xs 2*16*392 + mix 2*14*96 + ws 6*32*20 = 19072 words = 76288 B; 2 CTA/SM.
// ---------------------------------------------------------------------------
#define XS_PITCH 392
#define WS2_PITCH 20
#define MX2_XSBUF (16 * XS_PITCH)                  // 6272 words per buffer
#define MX2_XS    (2 * MX2_XSBUF)                  // 12544
#define MX2_MIXBUF (CH2 * 96)                      // 1344
#define MX2_MIX   (2 * MX2_MIXBUF)                 // 2688
#define MX2_WS    (Hh * 32 * WS2_PITCH)            // 3840
#define MX2_SMEM_BYTES ((MX2_XS + MX2_MIX + MX2_WS) * 4)

extern "C" __global__ void __launch_bounds__(384, 2)
mixer_kernel(float* __restrict__ out) {
    extern __shared__ float sm[];
    uint32_t* xs_u  = (uint32_t*)sm;                  // [2][16][392] tf32 bits
    float*    mix_s = sm + MX2_XS;                    // [2][14][96]
    uint32_t* ws_u  = (uint32_t*)(sm + MX2_XS + MX2_MIX); // [6][32][20] tf32 bits

    const int t    = threadIdx.x;
    const int b    = blockIdx.y;
    const int mt28 = blockIdx.x;          // 0..6
    const int lane = t & 31;
    const int warp = t >> 5;
    const int wh   = warp >> 1;           // h   0..5
    const int wm   = warp & 1;            // mtile 0..1
    const int qr   = lane >> 2;
    const int qc   = lane & 3;

    const uint32_t xs_a  = smem_u32p(xs_u);
    const uint32_t mix_a = smem_u32p(mix_s);

    float acc[8][4];
#pragma unroll
    for (int nt = 0; nt < 8; ++nt)
#pragma unroll
        for (int q = 0; q < 4; ++q) acc[nt][q] = 0.f;

    // zero pads once: xs rows 14-15 of both buffers; whole ws (n/m pads)
    for (int idx = t; idx < 2 * 2 * XS_PITCH; idx += 384) {
        int bp = idx / (2 * XS_PITCH), rem = idx % (2 * XS_PITCH);
        xs_u[bp * MX2_XSBUF + 14 * XS_PITCH + rem] = 0u;
    }
    for (int idx = t; idx < MX2_WS; idx += 384) ws_u[idx] = 0u;

    // prefetch chunk 0 into buffer 0
    {
        const uint4* srcx = (const uint4*)&g_xtf[(size_t)b * Nn * DIMc];
        for (int idx = t; idx < 1344; idx += 384) {
            int row = idx / 96, c4 = idx - (idx / 96) * 96;
            cp_async16(xs_a + (uint32_t)(row * XS_PITCH + c4 * 4) * 4u, srcx + idx);
        }
        const float4* srcm = (const float4*)&g_mix[(size_t)b * Nn * 96];
        if (t < 336) cp_async16(mix_a + (uint32_t)t * 16u, srcm + t);
        CP_COMMIT();
    }

    for (int c = 0; c < NCH2; ++c) {
        const int buf = c & 1;
        __syncthreads();   // prior phase2 done reading buf^1 (and c=0: pads done)
        if (c < NCH2 - 1) {
            const int n1 = (c + 1) * CH2;
            const int pb = buf ^ 1;
            const uint4* srcx = (const uint4*)&g_xtf[((size_t)b * Nn + n1) * DIMc];
            for (int idx = t; idx < 1344; idx += 384) {
                int row = idx / 96, c4 = idx - (idx / 96) * 96;
                cp_async16(xs_a + (uint32_t)(pb * MX2_XSBUF + row * XS_PITCH + c4 * 4) * 4u,
                           srcx + idx);
            }
            const float4* srcm = (const float4*)&g_mix[((size_t)b * Nn + n1) * 96];
            if (t < 336) cp_async16(mix_a + (uint32_t)(pb * MX2_MIXBUF + t * 4) * 4u, srcm + t);
            CP_COMMIT();
            CP_WAIT(1);    // chunk c landed; c+1 in flight
        } else {
            CP_WAIT(0);
        }
        __syncthreads();   // chunk c visible to all threads

        // phase 1: 392 (nl, ml) pairs over 384 threads (scalar fp32)
        const int n0 = c * CH2;
        const float* mixb = mix_s + buf * MX2_MIXBUF;
        for (int p = t; p < CH2 * TMX; p += 384) {
            int nl = p / TMX, ml = p - (p / TMX) * TMX;
            int mg = mt28 * TMX + ml;
            const float4* wv = (const float4*)&g_wbt[((size_t)(n0 + nl) * Nn + mg) * Kk];
            float4 w0 = __ldg(wv + 0), w1 = __ldg(wv + 1);
            float4 w2 = __ldg(wv + 2), w3 = __ldg(wv + 3);
#pragma unroll
            for (int hh = 0; hh < Hh; ++hh) {
                const float4* mx = (const float4*)&mixb[nl * 96 + hh * Kk];
                float4 m0 = mx[0], m1 = mx[1], m2 = mx[2], m3 = mx[3];
                float s = w0.x * m0.x;
                s = fmaf(w0.y, m0.y, s); s = fmaf(w0.z, m0.z, s); s = fmaf(w0.w, m0.w, s);
                s = fmaf(w1.x, m1.x, s); s = fmaf(w1.y, m1.y, s); s = fmaf(w1.z, m1.z, s); s = fmaf(w1.w, m1.w, s);
                s = fmaf(w2.x, m2.x, s); s = fmaf(w2.y, m2.y, s); s = fmaf(w2.z, m2.z, s); s = fmaf(w2.w, m2.w, s);
                s = fmaf(w3.x, m3.x, s); s = fmaf(w3.y, m3.y, s); s = fmaf(w3.z, m3.z, s); s = fmaf(w3.w, m3.w, s);
                ws_u[(hh * 32 + ml) * WS2_PITCH + nl] = tf32r(s);
            }
        }
        __syncthreads();

        // phase 2: tensor; 2 ktiles of 8 over this chunk's 16 padded n
        const uint32_t* xbuf = xs_u + buf * MX2_XSBUF;
#pragma unroll
        for (int kt = 0; kt < 2; ++kt) {
            int k8 = kt * 8;
            int arow = wm * 16 + qr;
            int acol = k8 + qc;
            uint32_t a0 = ws_u[(wh * 32 + arow)     * WS2_PITCH + acol];
            uint32_t a1 = ws_u[(wh * 32 + arow + 8) * WS2_PITCH + acol];
            uint32_t a2 = ws_u[(wh * 32 + arow)     * WS2_PITCH + acol + 4];
            uint32_t a3 = ws_u[(wh * 32 + arow + 8) * WS2_PITCH + acol + 4];
            int base0 = (k8 + qc)     * XS_PITCH + wh * 64 + qr;
            int base1 = (k8 + qc + 4) * XS_PITCH + wh * 64 + qr;
#pragma unroll
            for (int nt = 0; nt < 8; ++nt) {
                uint32_t b0 = xbuf[base0 + nt * 8];
                uint32_t b1 = xbuf[base1 + nt * 8];
                mma_tf32(acc[nt], a0, a1, a2, a3, b0, b1);
            }
        }
    }

    // epilogue
    const int r    = lane >> 2;
    const int mlo  = mt28 * TMX + wm * 16 + r;
    const int mhi  = mlo + 8;
    const bool hi_ok = (wm == 0) || (r < 4);
    const int colb = wh * 64 + 2 * (lane & 3);
    float* ob = out + (size_t)b * Nn * DIMc;
#pragma unroll
    for (int nt = 0; nt < 8; ++nt) {
        int cc = colb + nt * 8;
        *(float2*)&ob[(size_t)mlo * DIMc + cc] = make_float2(acc[nt][0], acc[nt][1]);
        if (hi_ok)
            *(float2*)&ob[(size_t)mhi * DIMc + cc] = make_float2(acc[nt][2], acc[nt][3]);
    }
}

// ---------------------------------------------------------------------------
extern "C" void kernel_launch(void* const* d_in, const int* in_sizes, int n_in,
                              void* d_out, int out_size) {
    const float* x  = (const float*)d_in[0];
    const float* W1 = (const float*)d_in[1];
    const float* b1 = (const float*)d_in[2];
    const float* W2 = (const float*)d_in[3];
    const float* b2 = (const float*)d_in[4];
    const float* wb = (const float*)d_in[5];
    float* out = (float*)d_out;

    cudaFuncSetAttribute((const void*)adapter_kernel,
                         cudaFuncAttributeMaxDynamicSharedMemorySize,
                         AT_SMEM_BYTES);
    cudaFuncSetAttribute((const void*)mixer_kernel,
                         cudaFuncAttributeMaxDynamicSharedMemorySize,
                         MX2_SMEM_BYTES);

    transpose_wb_kernel<<<(Nn * Nn + 255) / 256, 256>>>(wb);
    xtf_kernel<<<(XTF_F4 + 255) / 256, 256>>>(x);
    adapter_kernel<<<392, 128, AT_SMEM_BYTES>>>(x, W1, b1, W2, b2);
    mixer_kernel<<<dim3(NCH2 / 2, Bz), 384, MX2_SMEM_BYTES>>>(out);
}

// round 17
// speedup vs baseline: 1.1040x; 1.1040x over previous
#include <cuda_runtime.h>
#include <cstdint>

#define Bz   128
#define Nn   196
#define DIMc 384
#define Kk   16
#define Hh   6
#define TMX  28   // mixer m-tile width per CTA; 7*28 == 196
#define CH   28   // mixer n-chunk; 7*28 == 196
#define NCH  7

// Scratch (device globals — allocation-free)
__device__ __align__(16) float g_wbt[(size_t)Nn * Nn * Kk];      // [n][m][k]
__device__ __align__(16) float g_mix[(size_t)Bz * Nn * Hh * Kk]; // [b][n][h][k]

__device__ __forceinline__ uint32_t tf32r(float f) {
    uint32_t u;
    asm("cvt.rna.tf32.f32 %0, %1;" : "=r"(u) : "f"(f));
    return u;
}
__device__ __forceinline__ void mma_tf32(float* c, uint32_t a0, uint32_t a1,
                                         uint32_t a2, uint32_t a3,
                                         uint32_t b0, uint32_t b1) {
    asm volatile(
        "mma.sync.aligned.m16n8k8.row.col.f32.tf32.tf32.f32 "
        "{%0,%1,%2,%3}, {%4,%5,%6,%7}, {%8,%9}, {%0,%1,%2,%3};"
        : "+f"(c[0]), "+f"(c[1]), "+f"(c[2]), "+f"(c[3])
        : "r"(a0), "r"(a1), "r"(a2), "r"(a3), "r"(b0), "r"(b1));
}

// ---------------------------------------------------------------------------
// Kernel 1: weight_bank [k][n][m] -> g_wbt [n][m][k]  (k contiguous)
// ---------------------------------------------------------------------------
extern "C" __global__ void transpose_wb_kernel(const float* __restrict__ wb) {
    int t = blockIdx.x * 256 + threadIdx.x;
    if (t >= Nn * Nn) return;
    int n = t / Nn, m = t % Nn;
    float v[Kk];
#pragma unroll
    for (int k = 0; k < Kk; ++k)
        v[k] = wb[((size_t)k * Nn + n) * Nn + m];   // coalesced over m
    float4* dst = (float4*)&g_wbt[(size_t)t * Kk];
    dst[0] = make_float4(v[0],  v[1],  v[2],  v[3]);
    dst[1] = make_float4(v[4],  v[5],  v[6],  v[7]);
    dst[2] = make_float4(v[8],  v[9],  v[10], v[11]);
    dst[3] = make_float4(v[12], v[13], v[14], v[15]);
}

// ---------------------------------------------------------------------------
// Kernel 2: adapter v5 (tensor, mma.sync tf32). UNCHANGED from R14 (measured).
// ---------------------------------------------------------------------------
#define ATP_A 100
#define ATP_B 104
#define AT_SMEM_BYTES ((64 * ATP_A + 96 * ATP_B) * 4)

extern "C" __global__ void __launch_bounds__(128)
adapter_kernel(const float* __restrict__ x,
               const float* __restrict__ W1, const float* __restrict__ b1,
               const float* __restrict__ W2, const float* __restrict__ b2) {
    extern __shared__ float sm[];
    uint32_t* As = (uint32_t*)sm;                 // [64][100] tf32 bits / logits fp32
    uint32_t* Bs = (uint32_t*)(sm + 64 * ATP_A);  // [96][104] tf32 bits

    const int t    = threadIdx.x;
    const int lane = t & 31;
    const int warp = t >> 5;
    const int row0 = blockIdx.x * 64;

    const int qr = lane >> 2;
    const int qc = lane & 3;

    float acc[12][4];
#pragma unroll
    for (int nt = 0; nt < 12; ++nt)
#pragma unroll
        for (int q = 0; q < 4; ++q) acc[nt][q] = 0.f;

    for (int kc = 0; kc < 4; ++kc) {
        __syncthreads();
        for (int idx = t; idx < 1536; idx += 128) {
            int r = idx / 24, c4 = idx - (idx / 24) * 24;
            float4 v = *(const float4*)&x[(size_t)(row0 + r) * DIMc + kc * 96 + c4 * 4];
            *(uint4*)&As[r * ATP_A + c4 * 4] =
                make_uint4(tf32r(v.x), tf32r(v.y), tf32r(v.z), tf32r(v.w));
        }
        for (int idx = t; idx < 2304; idx += 128) {
            int k = idx / 24, n4 = idx - (idx / 24) * 24;
            float4 v = *(const float4*)&W1[(size_t)(kc * 96 + k) * 96 + n4 * 4];
            *(uint4*)&Bs[k * ATP_B + n4 * 4] =
                make_uint4(tf32r(v.x), tf32r(v.y), tf32r(v.z), tf32r(v.w));
        }
        __syncthreads();
#pragma unroll
        for (int kt = 0; kt < 12; ++kt) {
            int k8 = kt * 8;
            int arow = warp * 16 + qr;
            uint32_t a0 = As[arow * ATP_A + k8 + qc];
            uint32_t a1 = As[(arow + 8) * ATP_A + k8 + qc];
            uint32_t a2 = As[arow * ATP_A + k8 + qc + 4];
            uint32_t a3 = As[(arow + 8) * ATP_A + k8 + qc + 4];
            int bb0 = (k8 + qc) * ATP_B + qr;
            int bb1 = (k8 + qc + 4) * ATP_B + qr;
#pragma unroll
            for (int nt = 0; nt < 12; ++nt) {
                uint32_t b0v = Bs[bb0 + nt * 8];
                uint32_t b1v = Bs[bb1 + nt * 8];
                mma_tf32(acc[nt], a0, a1, a2, a3, b0v, b1v);
            }
        }
    }
    __syncthreads();

    {
        int rlo = warp * 16 + qr, rhi = rlo + 8;
#pragma unroll
        for (int nt = 0; nt < 12; ++nt) {
            int c0 = nt * 8 + 2 * qc, c1 = c0 + 1;
            float g0 = acc[nt][0] + __ldg(&b1[c0]);
            float g1 = acc[nt][1] + __ldg(&b1[c1]);
            float g2 = acc[nt][2] + __ldg(&b1[c0]);
            float g3 = acc[nt][3] + __ldg(&b1[c1]);
            g0 = 0.5f * g0 * (1.0f + erff(g0 * 0.7071067811865476f));
            g1 = 0.5f * g1 * (1.0f + erff(g1 * 0.7071067811865476f));
            g2 = 0.5f * g2 * (1.0f + erff(g2 * 0.7071067811865476f));
            g3 = 0.5f * g3 * (1.0f + erff(g3 * 0.7071067811865476f));
            As[rlo * ATP_A + c0] = tf32r(g0);
            As[rlo * ATP_A + c1] = tf32r(g1);
            As[rhi * ATP_A + c0] = tf32r(g2);
            As[rhi * ATP_A + c1] = tf32r(g3);
        }
        for (int idx = t; idx < 2304; idx += 128) {
            int k = idx / 24, n4 = idx - (idx / 24) * 24;
            float4 v = *(const float4*)&W2[(size_t)k * 96 + n4 * 4];
            *(uint4*)&Bs[k * ATP_B + n4 * 4] =
                make_uint4(tf32r(v.x), tf32r(v.y), tf32r(v.z), tf32r(v.w));
        }
    }
    __syncthreads();

#pragma unroll
    for (int nt = 0; nt < 12; ++nt)
#pragma unroll
        for (int q = 0; q < 4; ++q) acc[nt][q] = 0.f;
#pragma unroll
    for (int kt = 0; kt < 12; ++kt) {
        int k8 = kt * 8;
        int arow = warp * 16 + qr;
        uint32_t a0 = As[arow * ATP_A + k8 + qc];
        uint32_t a1 = As[(arow + 8) * ATP_A + k8 + qc];
        uint32_t a2 = As[arow * ATP_A + k8 + qc + 4];
        uint32_t a3 = As[(arow + 8) * ATP_A + k8 + qc + 4];
        int bb0 = (k8 + qc) * ATP_B + qr;
        int bb1 = (k8 + qc + 4) * ATP_B + qr;
#pragma unroll
        for (int nt = 0; nt < 12; ++nt) {
            uint32_t b0v = Bs[bb0 + nt * 8];
            uint32_t b1v = Bs[bb1 + nt * 8];
            mma_tf32(acc[nt], a0, a1, a2, a3, b0v, b1v);
        }
    }
    __syncthreads();

    {
        float* Lf = (float*)As;
        int rlo = warp * 16 + qr, rhi = rlo + 8;
#pragma unroll
        for (int nt = 0; nt < 12; ++nt) {
            int c0 = nt * 8 + 2 * qc, c1 = c0 + 1;
            Lf[rlo * ATP_A + c0] = acc[nt][0] + __ldg(&b2[c0]);
            Lf[rlo * ATP_A + c1] = acc[nt][1] + __ldg(&b2[c1]);
            Lf[rhi * ATP_A + c0] = acc[nt][2] + __ldg(&b2[c0]);
            Lf[rhi * ATP_A + c1] = acc[nt][3] + __ldg(&b2[c1]);
        }
    }
    __syncthreads();

    {
        const float* Lf = (const float*)As;
        for (int task = t; task < 384; task += 128) {
            int r = task / 6, h = task - (task / 6) * 6;
            float vals[Kk];
            float vmax = -1e30f;
#pragma unroll
            for (int k = 0; k < Kk; ++k) {
                vals[k] = Lf[r * ATP_A + k * Hh + h];
                vmax = fmaxf(vmax, vals[k]);
            }
            float s = 0.f;
#pragma unroll
            for (int k = 0; k < Kk; ++k) { vals[k] = __expf(vals[k] - vmax); s += vals[k]; }
            float inv = 1.0f / s;
            float4* dst = (float4*)&g_mix[(size_t)(row0 + r) * 96 + h * Kk];
            dst[0] = make_float4(vals[0]  * inv, vals[1]  * inv, vals[2]  * inv, vals[3]  * inv);
            dst[1] = make_float4(vals[4]  * inv, vals[5]  * inv, vals[6]  * inv, vals[7]  * inv);
            dst[2] = make_float4(vals[8]  * inv, vals[9]  * inv, vals[10] * inv, vals[11] * inv);
            dst[3] = make_float4(vals[12] * inv, vals[13] * inv, vals[14] * inv, vals[15] * inv);
        }
    }
}

// ---------------------------------------------------------------------------
// Kernel 3: mixer v6b — R12 structure (measured best) with ONE change:
// phase 1 assigns each thread (nl, ml-half) covering ml and ml+14, so the 6
// mix LDS.128 per nl are amortized over two m's (phase-1 LDS halved, LDG MLP
// 8). 392 tasks over 384 threads (near-perfect balance).
// CTA = (b, mt of 28 m), 384 threads, 2 CTAs/SM, smem 88576 B.
// ---------------------------------------------------------------------------
#define XS_PITCH 392
#define WS_PITCH 36
#define MXT_XS   (32 * XS_PITCH)            // 12544
#define MXT_WS   (Hh * 32 * WS_PITCH)       // 6912
#define MXT_MIX  (CH * 96)                  // 2688
#define MXT_SMEM_BYTES ((MXT_XS + MXT_WS + MXT_MIX) * 4)

extern "C" __global__ void __launch_bounds__(384, 2)
mixer_kernel(const float* __restrict__ x, float* __restrict__ out) {
    extern __shared__ float sm[];
    uint32_t* xs_u  = (uint32_t*)sm;                     // [32][392] tf32 bits
    uint32_t* ws_u  = (uint32_t*)(sm + MXT_XS);          // [h][32][36] tf32 bits
    float*    mix_s = sm + MXT_XS + MXT_WS;              // [28][96]

    const int t    = threadIdx.x;
    const int b    = blockIdx.y;
    const int mt28 = blockIdx.x;          // 0..6
    const int lane = t & 31;
    const int warp = t >> 5;
    const int wh   = warp >> 1;           // h   0..5
    const int wm   = warp & 1;            // mtile 0..1

    float acc[8][4];
#pragma unroll
    for (int nt = 0; nt < 8; ++nt)
#pragma unroll
        for (int q = 0; q < 4; ++q) acc[nt][q] = 0.f;

    // zero pads once: xs rows 28-31 (full rows) and whole ws (n/m pads)
    for (int idx = t; idx < 4 * XS_PITCH; idx += 384) xs_u[28 * XS_PITCH + idx] = 0u;
    for (int idx = t; idx < MXT_WS; idx += 384) ws_u[idx] = 0u;

    for (int c = 0; c < NCH; ++c) {
        const int n0 = c * CH;
        __syncthreads();
        // stage x chunk, tf32-rounded: 2688 float4
        {
            const float4* src = (const float4*)(x + ((size_t)b * Nn + n0) * DIMc);
#pragma unroll
            for (int i = 0; i < 7; ++i) {
                int idx = t + i * 384;
                int n = idx / 96, c4 = idx - n * 96;
                float4 v = src[idx];
                uint4 u = make_uint4(tf32r(v.x), tf32r(v.y), tf32r(v.z), tf32r(v.w));
                *(uint4*)&xs_u[n * XS_PITCH + c4 * 4] = u;
            }
        }
        // stage mix chunk: 672 float4
        {
            const float4* src = (const float4*)&g_mix[((size_t)b * Nn + n0) * 96];
            float4* dst = (float4*)mix_s;
            for (int idx = t; idx < 672; idx += 384) dst[idx] = src[idx];
        }
        __syncthreads();
        // phase 1: 392 (nl, ml-half) tasks, each covers ml and ml+14
        for (int q = t; q < CH * 14; q += 384) {
            int nl = q / 14, mh = q - (q / 14) * 14;
            int mgA = mt28 * TMX + mh;
            int mgB = mgA + 14;
            const float4* wvA = (const float4*)&g_wbt[((size_t)(n0 + nl) * Nn + mgA) * Kk];
            const float4* wvB = (const float4*)&g_wbt[((size_t)(n0 + nl) * Nn + mgB) * Kk];
            float4 a0 = __ldg(wvA + 0), a1 = __ldg(wvA + 1);
            float4 a2 = __ldg(wvA + 2), a3 = __ldg(wvA + 3);
            float4 b0 = __ldg(wvB + 0), b1 = __ldg(wvB + 1);
            float4 b2 = __ldg(wvB + 2), b3 = __ldg(wvB + 3);
#pragma unroll
            for (int hh = 0; hh < Hh; ++hh) {
                const float4* mx = (const float4*)&mix_s[nl * 96 + hh * Kk];
                float4 m0 = mx[0], m1 = mx[1], m2 = mx[2], m3 = mx[3];
                float sA = a0.x * m0.x;
                sA = fmaf(a0.y, m0.y, sA); sA = fmaf(a0.z, m0.z, sA); sA = fmaf(a0.w, m0.w, sA);
                sA = fmaf(a1.x, m1.x, sA); sA = fmaf(a1.y, m1.y, sA); sA = fmaf(a1.z, m1.z, sA); sA = fmaf(a1.w, m1.w, sA);
                sA = fmaf(a2.x, m2.x, sA); sA = fmaf(a2.y, m2.y, sA); sA = fmaf(a2.z, m2.z, sA); sA = fmaf(a2.w, m2.w, sA);
                sA = fmaf(a3.x, m3.x, sA); sA = fmaf(a3.y, m3.y, sA); sA = fmaf(a3.z, m3.z, sA); sA = fmaf(a3.w, m3.w, sA);
                float sB = b0.x * m0.x;
                sB = fmaf(b0.y, m0.y, sB); sB = fmaf(b0.z, m0.z, sB); sB = fmaf(b0.w, m0.w, sB);
                sB = fmaf(b1.x, m1.x, sB); sB = fmaf(b1.y, m1.y, sB); sB = fmaf(b1.z, m1.z, sB); sB = fmaf(b1.w, m1.w, sB);
                sB = fmaf(b2.x, m2.x, sB); sB = fmaf(b2.y, m2.y, sB); sB = fmaf(b2.z, m2.z, sB); sB = fmaf(b2.w, m2.w, sB);
                sB = fmaf(b3.x, m3.x, sB); sB = fmaf(b3.y, m3.y, sB); sB = fmaf(b3.z, m3.z, sB); sB = fmaf(b3.w, m3.w, sB);
                ws_u[(hh * 32 + mh)      * WS_PITCH + nl] = tf32r(sA);
                ws_u[(hh * 32 + mh + 14) * WS_PITCH + nl] = tf32r(sB);
            }
        }
        __syncthreads();
        // phase 2: tensor. 4 ktiles of 8 within this chunk's 32 padded n.
#pragma unroll
        for (int kt = 0; kt < 4; ++kt) {
            int k8 = kt * 8;
            int arow = wm * 16 + (lane >> 2);
            int acol = k8 + (lane & 3);
            uint32_t a0 = ws_u[(wh * 32 + arow)     * WS_PITCH + acol];
            uint32_t a1 = ws_u[(wh * 32 + arow + 8) * WS_PITCH + acol];
            uint32_t a2 = ws_u[(wh * 32 + arow)     * WS_PITCH + acol + 4];
            uint32_t a3 = ws_u[(wh * 32 + arow + 8) * WS_PITCH + acol + 4];
            int base0 = (k8 + (lane & 3))     * XS_PITCH + wh * 64 + (lane >> 2);
            int base1 = (k8 + (lane & 3) + 4) * XS_PITCH + wh * 64 + (lane >> 2);
#pragma unroll
            for (int nt = 0; nt < 8; ++nt) {
                uint32_t b0 = xs_u[base0 + nt * 8];
                uint32_t b1 = xs_u[base1 + nt * 8];
                mma_tf32(acc[nt], a0, a1, a2, a3, b0, b1);
            }
        }
    }

    const int r    = lane >> 2;
    const int mlo  = mt28 * TMX + wm * 16 + r;
    const int mhi  = mlo + 8;
    const bool hi_ok = (wm == 0) || (r < 4);
    const int colb = wh * 64 + 2 * (lane & 3);
    float* ob = out + (size_t)b * Nn * DIMc;
#pragma unroll
    for (int nt = 0; nt < 8; ++nt) {
        int cc = colb + nt * 8;
        *(float2*)&ob[(size_t)mlo * DIMc + cc] = make_float2(acc[nt][0], acc[nt][1]);
        if (hi_ok)
            *(float2*)&ob[(size_t)mhi * DIMc + cc] = make_float2(acc[nt][2], acc[nt][3]);
    }
}

// ---------------------------------------------------------------------------
extern "C" void kernel_launch(void* const* d_in, const int* in_sizes, int n_in,
                              void* d_out, int out_size) {
    const float* x  = (const float*)d_in[0];
    const float* W1 = (const float*)d_in[1];
    const float* b1 = (const float*)d_in[2];
    const float* W2 = (const float*)d_in[3];
    const float* b2 = (const float*)d_in[4];
    const float* wb = (const float*)d_in[5];
    float* out = (float*)d_out;

    cudaFuncSetAttribute((const void*)adapter_kernel,
                         cudaFuncAttributeMaxDynamicSharedMemorySize,
                         AT_SMEM_BYTES);
    cudaFuncSetAttribute((const void*)mixer_kernel,
                         cudaFuncAttributeMaxDynamicSharedMemorySize,
                         MXT_SMEM_BYTES);

    transpose_wb_kernel<<<(Nn * Nn + 255) / 256, 256>>>(wb);
    adapter_kernel<<<392, 128, AT_SMEM_BYTES>>>(x, W1, b1, W2, b2);
    mixer_kernel<<<dim3(NCH, Bz), 384, MXT_SMEM_BYTES>>>(x, out);
}